// round 11
// baseline (speedup 1.0000x reference)
#include <cuda_runtime.h>
#include <cuda_fp16.h>
#include <cstdint>
#include <math.h>

// ============================================================================
// Problem constants
// ============================================================================
#define BB 4
#define SS 2048
#define DD 1024
#define HH 16
#define HDIM 64
#define MROWS (BB * SS)     /* 8192 */
#define NHEAD (HH * HDIM)   /* 1024 */

// Scratch (device globals: allocation-free)
__device__ __align__(16) __half g_qh[MROWS * NHEAD];     // fp16 q
__device__ __align__(16) __half g_kh[MROWS * NHEAD];     // fp16 k
__device__ __align__(16) float  g_v [MROWS * NHEAD];     // fp32 v
__device__ __align__(16) __half g_ctxh[MROWS * NHEAD];   // fp16 ctx

// ============================================================================
// Helpers
// ============================================================================
__device__ __forceinline__ uint32_t smem_u32(const void* p) {
    uint32_t a;
    asm("{ .reg .u64 t; cvta.to.shared.u64 t, %1; cvt.u32.u64 %0, t; }"
        : "=r"(a) : "l"(p));
    return a;
}

__device__ __forceinline__ uint32_t pack_f16x2(float lo, float hi) {
    uint32_t r;
    asm("cvt.rn.f16x2.f32 %0, %1, %2;" : "=r"(r) : "f"(hi), "f"(lo));
    return r;
}

__device__ __forceinline__ void mma_f16(float* c, const uint32_t* a, const uint32_t* b) {
    asm volatile(
        "mma.sync.aligned.m16n8k16.row.col.f32.f16.f16.f32 "
        "{%0,%1,%2,%3}, {%4,%5,%6,%7}, {%8,%9}, {%0,%1,%2,%3};"
        : "+f"(c[0]), "+f"(c[1]), "+f"(c[2]), "+f"(c[3])
        : "r"(a[0]), "r"(a[1]), "r"(a[2]), "r"(a[3]), "r"(b[0]), "r"(b[1]));
}

__device__ __forceinline__ void ldm_x4(uint32_t* r, uint32_t addr) {
    asm volatile(
        "ldmatrix.sync.aligned.m8n8.x4.shared.b16 {%0,%1,%2,%3}, [%4];"
        : "=r"(r[0]), "=r"(r[1]), "=r"(r[2]), "=r"(r[3]) : "r"(addr));
}

#define CP16(dst, src) \
    asm volatile("cp.async.cg.shared.global [%0], [%1], 16;" \
        :: "r"(dst), "l"(src) : "memory")
#define CP_COMMIT() asm volatile("cp.async.commit_group;" ::: "memory")
#define CP_WAIT1()  asm volatile("cp.async.wait_group 1;" ::: "memory")
#define CP_WAIT0()  asm volatile("cp.async.wait_group 0;" ::: "memory")

// ============================================================================
// FP16 tensor-core GEMM with in-flight fp32 -> fp16 conversion.
//   C[8192 x 1024] = (A @ W + bias) * scale
// A: fp32 x [M][K] (AF32=1) or fp16 [M][K] (AF32=0), row-major.
// B: fp32 W [K][N] natural row-major (no pre-transpose) — B-frags built by
//    row-strided LDS + cvt pack (stride 132 words: conflict-free).
// CTA 128x128, BK=32, 8 warps (2Mx4N), warp tile 64x32, m16n8k16, 3 stages.
// Numerics: identical cvt.rn ops as the former prepass -> bit-identical C.
// ============================================================================
template<bool AF32>
struct GP {
    static constexpr int ASTR  = AF32 ? 36 : 20;        // words per A smem row
    static constexpr int AW    = 128 * ASTR;            // A tile words
    static constexpr int BSTR  = 132;                   // words per B smem row
    static constexpr int BW    = 32 * BSTR;             // B tile words
    static constexpr int STAGE = (AW + BW) * 4;         // bytes
    static constexpr int SMEM  = 3 * STAGE;
};

template<bool AF32>
__device__ __forceinline__ void
gemm_body(char* smraw, const void* __restrict__ Avoid,
          const float* __restrict__ W,       // fp32 [K][N] natural
          const float* __restrict__ bias,
          float* __restrict__ Cf, __half* __restrict__ Ch,
          float scale, int outHalf, int bx, int by)
{
    using P = GP<AF32>;
    const uint32_t smb = smem_u32(smraw);

    const int tid  = threadIdx.x;
    const int lane = tid & 31;
    const int wid  = tid >> 5;
    const int wm   = wid & 1;
    const int wn   = wid >> 1;
    const int gid  = lane >> 2;
    const int tig  = lane & 3;
    const int m0   = by * 128;
    const int n0   = bx * 128;

    float acc[4][4][4];
    #pragma unroll
    for (int i = 0; i < 4; ++i)
        #pragma unroll
        for (int j = 0; j < 4; ++j)
            #pragma unroll
            for (int r = 0; r < 4; ++r) acc[i][j][r] = 0.f;

    const float*  Af32 = (const float*) Avoid;
    const __half* Af16 = (const __half*)Avoid;
    const float*  Wg   = W + n0;

    auto load_stage = [&](int s, int kt) {
        const uint32_t as = smb + (uint32_t)s * P::STAGE;
        const uint32_t bs = as + P::AW * 4;
        if (AF32) {
            // A tile 128x32 fp32 = 1024 chunks, 4/thread
            #pragma unroll
            for (int i = 0; i < 4; ++i) {
                int idx = tid + i * 256;
                int r = idx >> 3, c = (idx & 7) << 2;
                CP16(as + (uint32_t)(r * P::ASTR + c) * 4,
                     Af32 + (size_t)(m0 + r) * 1024 + kt * 32 + c);
            }
        } else {
            // A tile 128x32 fp16 = 512 chunks, 2/thread
            #pragma unroll
            for (int i = 0; i < 2; ++i) {
                int idx = tid + i * 256;
                int r = idx >> 2, c = (idx & 3) << 3;   // c in halves
                CP16(as + (uint32_t)(r * P::ASTR * 4 + c * 2),
                     Af16 + (size_t)(m0 + r) * 1024 + kt * 32 + c);
            }
        }
        // B tile 32x128 fp32 (natural W rows) = 1024 chunks, 4/thread
        #pragma unroll
        for (int i = 0; i < 4; ++i) {
            int idx = tid + i * 256;
            int r = idx >> 5, c = (idx & 31) << 2;
            CP16(bs + (uint32_t)(r * P::BSTR + c) * 4,
                 Wg + (size_t)(kt * 32 + r) * 1024 + c);
        }
    };

    load_stage(0, 0); CP_COMMIT();
    load_stage(1, 1); CP_COMMIT();

    int st = 0;
    for (int kt = 0; kt < 32; ++kt) {
        CP_WAIT1();
        __syncthreads();

        if (kt + 2 < 32) {
            int sn = st + 2; if (sn >= 3) sn -= 3;
            load_stage(sn, kt + 2);
        }
        CP_COMMIT();

        const char* stg = smraw + st * P::STAGE;
        const float* bF = (const float*)(stg + P::AW * 4);

        #pragma unroll
        for (int k16 = 0; k16 < 2; ++k16) {
            uint32_t a[4][4], b[4][2];
            if (AF32) {
                const float* aF = (const float*)stg;
                #pragma unroll
                for (int i = 0; i < 4; ++i) {
                    const float* ap = aF + (wm * 64 + i * 16 + gid) * P::ASTR
                                         + k16 * 16 + 2 * tig;
                    float2 v0 = *(const float2*)ap;
                    float2 v1 = *(const float2*)(ap + 8 * P::ASTR);
                    float2 v2 = *(const float2*)(ap + 8);
                    float2 v3 = *(const float2*)(ap + 8 * P::ASTR + 8);
                    a[i][0] = pack_f16x2(v0.x, v0.y);
                    a[i][1] = pack_f16x2(v1.x, v1.y);
                    a[i][2] = pack_f16x2(v2.x, v2.y);
                    a[i][3] = pack_f16x2(v3.x, v3.y);
                }
            } else {
                const uint32_t* a32 = (const uint32_t*)stg;
                #pragma unroll
                for (int i = 0; i < 4; ++i) {
                    const uint32_t* ap = a32 + (wm * 64 + i * 16 + gid) * P::ASTR
                                             + k16 * 8 + tig;
                    a[i][0] = ap[0];
                    a[i][1] = ap[8 * P::ASTR];
                    a[i][2] = ap[4];
                    a[i][3] = ap[8 * P::ASTR + 4];
                }
            }
            #pragma unroll
            for (int j = 0; j < 4; ++j) {
                const float* bp = bF + (k16 * 16 + 2 * tig) * P::BSTR
                                     + wn * 32 + j * 8 + gid;
                b[j][0] = pack_f16x2(bp[0],            bp[P::BSTR]);
                b[j][1] = pack_f16x2(bp[8 * P::BSTR],  bp[9 * P::BSTR]);
            }
            #pragma unroll
            for (int i = 0; i < 4; ++i)
                #pragma unroll
                for (int j = 0; j < 4; ++j)
                    mma_f16(acc[i][j], a[i], b[j]);
        }
        ++st; if (st >= 3) st -= 3;
    }
    CP_WAIT0();

    #pragma unroll
    for (int i = 0; i < 4; ++i) {
        const int row = m0 + wm * 64 + i * 16 + gid;
        #pragma unroll
        for (int j = 0; j < 4; ++j) {
            const int col = n0 + wn * 32 + j * 8 + (tig << 1);
            const float b0 = bias[col], b1 = bias[col + 1];
            float v00 = (acc[i][j][0] + b0) * scale;
            float v01 = (acc[i][j][1] + b1) * scale;
            float v10 = (acc[i][j][2] + b0) * scale;
            float v11 = (acc[i][j][3] + b1) * scale;
            if (outHalf) {
                *(uint32_t*)(Ch + (size_t)row * 1024 + col)       = pack_f16x2(v00, v01);
                *(uint32_t*)(Ch + (size_t)(row + 8) * 1024 + col) = pack_f16x2(v10, v11);
            } else {
                *(float2*)(Cf + (size_t)row * 1024 + col)       = make_float2(v00, v01);
                *(float2*)(Cf + (size_t)(row + 8) * 1024 + col) = make_float2(v10, v11);
            }
        }
    }
}

// Merged QKV (A = raw fp32 x, B = raw fp32 W): blockIdx.z selects {q, k, v}
__global__ void __launch_bounds__(256, 2)
gemm_qkv(const float* __restrict__ x,
         const float* __restrict__ Wq, const float* __restrict__ Wk,
         const float* __restrict__ Wv,
         const float* __restrict__ bq, const float* __restrict__ bk,
         const float* __restrict__ bv,
         __half* __restrict__ qh, __half* __restrict__ kh,
         float* __restrict__ vf)
{
    extern __shared__ char smraw[];
    const int z = blockIdx.z;
    const float* W   = (z == 0) ? Wq : (z == 1) ? Wk : Wv;
    const float* bia = (z == 0) ? bq : (z == 1) ? bk : bv;
    if (z == 2)
        gemm_body<true>(smraw, x, W, bia, vf, nullptr, 1.0f, 0,
                        blockIdx.x, blockIdx.y);
    else
        gemm_body<true>(smraw, x, W, bia, nullptr, (z == 0) ? qh : kh,
                        (z == 0) ? 0.125f : 1.0f, 1, blockIdx.x, blockIdx.y);
}

// Output projection (A = fp16 ctx, B = raw fp32 Wo, fp32 out)
__global__ void __launch_bounds__(256, 2)
gemm_out(const __half* __restrict__ A, const float* __restrict__ Wo,
         const float* __restrict__ bias, float* __restrict__ Cf)
{
    extern __shared__ char smraw[];
    gemm_body<false>(smraw, A, Wo, bias, Cf, nullptr, 1.0f, 0,
                     blockIdx.x, blockIdx.y);
}

// ============================================================================
// FP16 flash attention (unchanged — proven, tensor-bound at ~96% of ceiling).
// ============================================================================
#define FQ 128
#define QK_STR 36
#define VS_STR 68
#define VT_STR 36
#define FL_SMEM (128*QK_STR*4 + 2*64*QK_STR*4 + 64*VS_STR*4 + 64*VT_STR*4)

#define FCP_COMMIT() asm volatile("cp.async.commit_group;" ::: "memory")
#define FCP_WAIT0()  asm volatile("cp.async.wait_group 0;" ::: "memory")

__global__ void __launch_bounds__(256, 2)
flash_tc(const __half* __restrict__ Q, const __half* __restrict__ K,
         const float* __restrict__ V, __half* __restrict__ O)
{
    extern __shared__ char smraw[];
    uint32_t* Qs32 = (uint32_t*)smraw;
    uint32_t* Ks32 = Qs32 + 128 * QK_STR;
    float*    Vs   = (float*)(Ks32 + 2 * 64 * QK_STR);
    uint32_t* Vt   = (uint32_t*)(Vs + 64 * VS_STR);

    const uint32_t smb    = smem_u32(smraw);
    const uint32_t ks_smb = smb + 128 * QK_STR * 4;
    const uint32_t vs_smb = ks_smb + 2 * 64 * QK_STR * 4;
    const uint32_t vt_smb = vs_smb + 64 * VS_STR * 4;

    const int tid  = threadIdx.x;
    const int w    = tid >> 5;
    const int lane = tid & 31;
    const int gid  = lane >> 2;
    const int tig  = lane & 3;
    const int bh   = blockIdx.y;
    const int b    = bh >> 4;
    const int h    = bh & 15;
    const int q0   = blockIdx.x * FQ;

    const __half* Qg = Q + ((size_t)b * SS + q0) * NHEAD + h * HDIM;
    const __half* Kg = K + (size_t)b * SS * NHEAD + h * HDIM;
    const float*  Vg = V + (size_t)b * SS * NHEAD + h * HDIM;

    auto load_k = [&](uint32_t dstbase, const __half* src) {
        #pragma unroll
        for (int i = 0; i < 2; ++i) {
            int idx = tid + i * 256;
            int r = idx >> 3, c = (idx & 7) << 3;
            CP16(dstbase + (uint32_t)(r * QK_STR * 4 + c * 2),
                 src + (size_t)r * NHEAD + c);
        }
    };
    auto load_v = [&](const float* src) {
        #pragma unroll
        for (int i = 0; i < 4; ++i) {
            int idx = tid + i * 256;
            int r = idx >> 4, c = (idx & 15) << 2;
            CP16(vs_smb + (uint32_t)(r * VS_STR + c) * 4,
                 src + (size_t)r * NHEAD + c);
        }
    };

    load_k(ks_smb, Kg);
    load_v(Vg);
    FCP_COMMIT();

    #pragma unroll
    for (int i = 0; i < 4; ++i) {
        int idx = tid + i * 256;
        int r = idx >> 3, c8 = idx & 7;
        uint4 t = *(const uint4*)(Qg + (size_t)r * NHEAD + c8 * 8);
        *(uint4*)(Qs32 + r * QK_STR + c8 * 4) = t;
    }

    float m_[2] = {-1e30f, -1e30f};
    float l_[2] = {0.f, 0.f};
    float o[8][4];
    #pragma unroll
    for (int nt = 0; nt < 8; ++nt)
        #pragma unroll
        for (int r = 0; r < 4; ++r) o[nt][r] = 0.f;

    const int qr = w * 16 + gid;
    const int jp = 4 * w + tig;

    const int arow = w * 16 + (lane & 7) + (((lane >> 3) & 1) << 3);
    const uint32_t q_lm = smb + (uint32_t)(arow * QK_STR) * 4
                              + (((lane >> 4) & 1) << 4);
    const int brow = (lane & 7) + (((lane >> 4) & 1) << 3);
    const uint32_t bcol = (((lane >> 3) & 1) << 4);
    const uint32_t k_lm0 = ks_smb + (uint32_t)(brow * QK_STR) * 4 + bcol;
    const uint32_t v_lm  = vt_smb + (uint32_t)(brow * VT_STR) * 4 + bcol;

    for (int it = 0; it < 32; ++it) {
        const int t0 = it * 64;
        FCP_WAIT0();
        __syncthreads();

        #pragma unroll
        for (int itd = 0; itd < 8; ++itd) {
            int d = gid + 8 * itd;
            float lo = Vs[(2 * jp)     * VS_STR + d];
            float hi = Vs[(2 * jp + 1) * VS_STR + d];
            Vt[d * VT_STR + jp] = pack_f16x2(lo, hi);
        }
        __syncthreads();

        if (it + 1 < 32) {
            load_k(ks_smb + (uint32_t)(((it + 1) & 1) * 64 * QK_STR) * 4,
                   Kg + (size_t)(t0 + 64) * NHEAD);
            load_v(Vg + (size_t)(t0 + 64) * NHEAD);
        }
        FCP_COMMIT();

        const uint32_t klm = k_lm0 + (uint32_t)((it & 1) * 64 * QK_STR) * 4;

        float s[8][4];
        #pragma unroll
        for (int nt = 0; nt < 8; ++nt)
            #pragma unroll
            for (int r = 0; r < 4; ++r) s[nt][r] = 0.f;

        #pragma unroll
        for (int ks = 0; ks < 4; ++ks) {
            uint32_t a[4];
            ldm_x4(a, q_lm + ks * 32);
            #pragma unroll
            for (int p = 0; p < 4; ++p) {
                uint32_t kb[4];
                ldm_x4(kb, klm + (uint32_t)(p * 16 * QK_STR) * 4 + ks * 32);
                mma_f16(s[2 * p],     a, kb);
                mma_f16(s[2 * p + 1], a, kb + 2);
            }
        }

        #pragma unroll
        for (int hh = 0; hh < 2; ++hh) {
            const int c0 = 2 * hh, c1 = c0 + 1;
            float mt = fmaxf(s[0][c0], s[0][c1]);
            #pragma unroll
            for (int nt = 1; nt < 8; ++nt)
                mt = fmaxf(mt, fmaxf(s[nt][c0], s[nt][c1]));
            mt = fmaxf(mt, __shfl_xor_sync(0xffffffffu, mt, 1));
            mt = fmaxf(mt, __shfl_xor_sync(0xffffffffu, mt, 2));
            float mnew = fmaxf(m_[hh], mt);
            float corr = __expf(m_[hh] - mnew);
            m_[hh] = mnew;
            float ls = 0.f;
            #pragma unroll
            for (int nt = 0; nt < 8; ++nt) {
                s[nt][c0] = __expf(s[nt][c0] - mnew);
                s[nt][c1] = __expf(s[nt][c1] - mnew);
                ls += s[nt][c0] + s[nt][c1];
            }
            ls += __shfl_xor_sync(0xffffffffu, ls, 1);
            ls += __shfl_xor_sync(0xffffffffu, ls, 2);
            l_[hh] = l_[hh] * corr + ls;
            #pragma unroll
            for (int nt = 0; nt < 8; ++nt) {
                o[nt][c0] *= corr;
                o[nt][c1] *= corr;
            }
        }

        uint32_t pa[4][4];
        #pragma unroll
        for (int kc = 0; kc < 4; ++kc) {
            pa[kc][0] = pack_f16x2(s[2 * kc][0],     s[2 * kc][1]);
            pa[kc][1] = pack_f16x2(s[2 * kc][2],     s[2 * kc][3]);
            pa[kc][2] = pack_f16x2(s[2 * kc + 1][0], s[2 * kc + 1][1]);
            pa[kc][3] = pack_f16x2(s[2 * kc + 1][2], s[2 * kc + 1][3]);
        }

        #pragma unroll
        for (int kc = 0; kc < 4; ++kc) {
            #pragma unroll
            for (int p = 0; p < 4; ++p) {
                uint32_t vb[4];
                ldm_x4(vb, v_lm + (uint32_t)(p * 16 * VT_STR) * 4 + kc * 32);
                mma_f16(o[2 * p],     pa[kc], vb);
                mma_f16(o[2 * p + 1], pa[kc], vb + 2);
            }
        }
    }

    const float inv0 = 1.f / l_[0];
    const float inv1 = 1.f / l_[1];
    __half* Og = O + ((size_t)b * SS + q0 + qr) * NHEAD + h * HDIM;
    #pragma unroll
    for (int nt = 0; nt < 8; ++nt) {
        *(uint32_t*)(Og + nt * 8 + 2 * tig) =
            pack_f16x2(o[nt][0] * inv0, o[nt][1] * inv0);
        *(uint32_t*)(Og + (size_t)8 * NHEAD + nt * 8 + 2 * tig) =
            pack_f16x2(o[nt][2] * inv1, o[nt][3] * inv1);
    }
}

// ============================================================================
extern "C" void kernel_launch(void* const* d_in, const int* in_sizes, int n_in,
                              void* d_out, int out_size)
{
    (void)in_sizes; (void)n_in; (void)out_size;
    const float* x  = (const float*)d_in[0];
    const float* Wq = (const float*)d_in[1];
    const float* bq = (const float*)d_in[2];
    const float* Wk = (const float*)d_in[3];
    const float* bk = (const float*)d_in[4];
    const float* Wv = (const float*)d_in[5];
    const float* bv = (const float*)d_in[6];
    const float* Wo = (const float*)d_in[7];
    const float* bo = (const float*)d_in[8];
    float* out = (float*)d_out;

    __half *qh, *kh, *ctxh;
    float  *vp;
    cudaGetSymbolAddress((void**)&qh,   g_qh);
    cudaGetSymbolAddress((void**)&kh,   g_kh);
    cudaGetSymbolAddress((void**)&vp,   g_v);
    cudaGetSymbolAddress((void**)&ctxh, g_ctxh);

    cudaFuncSetAttribute(gemm_qkv,
                         cudaFuncAttributeMaxDynamicSharedMemorySize, GP<true>::SMEM);
    cudaFuncSetAttribute(gemm_out,
                         cudaFuncAttributeMaxDynamicSharedMemorySize, GP<false>::SMEM);
    cudaFuncSetAttribute(flash_tc,
                         cudaFuncAttributeMaxDynamicSharedMemorySize, FL_SMEM);

    // Merged QKV projections straight from raw fp32 inputs (no prepass)
    dim3 qkvgrid(NHEAD / 128, MROWS / 128, 3);  // (8, 64, 3) = 1536 CTAs
    gemm_qkv<<<qkvgrid, 256, GP<true>::SMEM>>>(x, Wq, Wk, Wv, bq, bk, bv,
                                               qh, kh, vp);

    // FP16 flash attention; ctx out fp16
    flash_tc<<<dim3(SS / FQ, BB * HH), 256, FL_SMEM>>>(qh, kh, vp, ctxh);

    // Output projection straight from raw fp32 Wo (fp32 out)
    dim3 ggrid(NHEAD / 128, MROWS / 128);
    gemm_out<<<ggrid, 256, GP<false>::SMEM>>>(ctxh, Wo, bo, out);
}

// round 12
// speedup vs baseline: 1.2362x; 1.2362x over previous
#include <cuda_runtime.h>
#include <cuda_fp16.h>
#include <cstdint>
#include <math.h>

// ============================================================================
// Problem constants
// ============================================================================
#define BB 4
#define SS 2048
#define DD 1024
#define HH 16
#define HDIM 64
#define MROWS (BB * SS)     /* 8192 */
#define NHEAD (HH * HDIM)   /* 1024 */

// Scratch (device globals: allocation-free)
__device__ __align__(16) __half g_wt[4][DD * NHEAD];     // fp16 W^T (q,k,v,o)
__device__ __align__(16) __half g_qh[MROWS * NHEAD];     // fp16 q
__device__ __align__(16) __half g_kh[MROWS * NHEAD];     // fp16 k
__device__ __align__(16) float  g_v [MROWS * NHEAD];     // fp32 v
__device__ __align__(16) __half g_ctxh[MROWS * NHEAD];   // fp16 ctx

// ============================================================================
// Helpers
// ============================================================================
__device__ __forceinline__ uint32_t smem_u32(const void* p) {
    uint32_t a;
    asm("{ .reg .u64 t; cvta.to.shared.u64 t, %1; cvt.u32.u64 %0, t; }"
        : "=r"(a) : "l"(p));
    return a;
}

__device__ __forceinline__ uint32_t pack_f16x2(float lo, float hi) {
    uint32_t r;
    asm("cvt.rn.f16x2.f32 %0, %1, %2;" : "=r"(r) : "f"(hi), "f"(lo));
    return r;
}

__device__ __forceinline__ void mma_f16(float* c, const uint32_t* a, const uint32_t* b) {
    asm volatile(
        "mma.sync.aligned.m16n8k16.row.col.f32.f16.f16.f32 "
        "{%0,%1,%2,%3}, {%4,%5,%6,%7}, {%8,%9}, {%0,%1,%2,%3};"
        : "+f"(c[0]), "+f"(c[1]), "+f"(c[2]), "+f"(c[3])
        : "r"(a[0]), "r"(a[1]), "r"(a[2]), "r"(a[3]), "r"(b[0]), "r"(b[1]));
}

__device__ __forceinline__ void ldm_x4(uint32_t* r, uint32_t addr) {
    asm volatile(
        "ldmatrix.sync.aligned.m8n8.x4.shared.b16 {%0,%1,%2,%3}, [%4];"
        : "=r"(r[0]), "=r"(r[1]), "=r"(r[2]), "=r"(r[3]) : "r"(addr));
}

#define CP16(dst, src) \
    asm volatile("cp.async.cg.shared.global [%0], [%1], 16;" \
        :: "r"(dst), "l"(src) : "memory")
#define CP_COMMIT() asm volatile("cp.async.commit_group;" ::: "memory")
#define CP_WAIT2()  asm volatile("cp.async.wait_group 2;" ::: "memory")
#define CP_WAIT1()  asm volatile("cp.async.wait_group 1;" ::: "memory")
#define CP_WAIT0()  asm volatile("cp.async.wait_group 0;" ::: "memory")

// ============================================================================
// Prepass (single launch, 4096 blocks): W{q,k,v,o} fp32 -> fp16 transposed.
// (x conversion eliminated — QKV GEMM converts A in-flight.)
// ============================================================================
__global__ void __launch_bounds__(256)
prepass(const float* __restrict__ Wq, const float* __restrict__ Wk,
        const float* __restrict__ Wv, const float* __restrict__ Wo,
        __half* __restrict__ wt)
{
    __shared__ float tbuf[32][33];
    const int bid  = blockIdx.x;
    const int wsel = bid >> 10;
    const int t    = bid & 1023;
    const float* W = (wsel == 0) ? Wq : (wsel == 1) ? Wk : (wsel == 2) ? Wv : Wo;
    __half* Wt = wt + (size_t)wsel * DD * NHEAD;

    const int bx = (t & 31) * 32, by = (t >> 5) * 32;
    const int tx = threadIdx.x & 31, ty = threadIdx.x >> 5;
    const int xc = bx + tx;
    #pragma unroll
    for (int i = 0; i < 32; i += 8)
        tbuf[ty + i][tx] = W[(size_t)(by + ty + i) * 1024 + xc];
    __syncthreads();
    const int xo = by + tx;
    #pragma unroll
    for (int i = 0; i < 32; i += 8)
        Wt[(size_t)(bx + ty + i) * 1024 + xo] =
            __float2half(tbuf[tx][ty + i]);
}

// ============================================================================
// FP16 tensor-core GEMM. A: fp32 (AF32, converted in-flight, stride 40 —
// conflict-free LDS.64 phases) or fp16 (R10 path, stride 20). B: fp16 W^T
// (R10's proven path). CTA 128x128, BK=32, 8 warps, m16n8k16.
// AF32: 3 stages (30KB each); fp16: 4 stages (20KB each).
// ============================================================================
#define B_STR 20                       /* b32 words per fp16 B smem row */
#define B_WORDS (128 * B_STR)

template<bool AF32>
struct GP {
    static constexpr int ASTR  = AF32 ? 40 : 20;   // words per A smem row
    static constexpr int AW    = 128 * ASTR;
    static constexpr int STAGE = (AW + B_WORDS) * 4;
    static constexpr int NSTG  = AF32 ? 3 : 4;
    static constexpr int SMEM  = NSTG * STAGE;
};

template<bool AF32>
__device__ __forceinline__ void
gemm_body(char* smraw, const void* __restrict__ Avoid,
          const __half* __restrict__ Wt,   // fp16 [N][K] transposed
          const float* __restrict__ bias,
          float* __restrict__ Cf, __half* __restrict__ Ch,
          float scale, int outHalf, int bx, int by)
{
    using P = GP<AF32>;
    const uint32_t smb = smem_u32(smraw);

    const int tid  = threadIdx.x;
    const int lane = tid & 31;
    const int wid  = tid >> 5;
    const int wm   = wid & 1;
    const int wn   = wid >> 1;
    const int gid  = lane >> 2;
    const int tig  = lane & 3;
    const int m0   = by * 128;
    const int n0   = bx * 128;

    float acc[4][4][4];
    #pragma unroll
    for (int i = 0; i < 4; ++i)
        #pragma unroll
        for (int j = 0; j < 4; ++j)
            #pragma unroll
            for (int r = 0; r < 4; ++r) acc[i][j][r] = 0.f;

    const float*  Af32 = (const float*) Avoid;
    const __half* Af16 = (const __half*)Avoid;
    const __half* Wg   = Wt + (size_t)n0 * 1024;

    auto load_stage = [&](int s, int kt) {
        const uint32_t as = smb + (uint32_t)s * P::STAGE;
        const uint32_t bs = as + P::AW * 4;
        if (AF32) {
            // A tile 128x32 fp32 = 1024 chunks, 4/thread, stride 40 words
            #pragma unroll
            for (int i = 0; i < 4; ++i) {
                int idx = tid + i * 256;
                int r = idx >> 3, c = (idx & 7) << 2;
                CP16(as + (uint32_t)(r * P::ASTR + c) * 4,
                     Af32 + (size_t)(m0 + r) * 1024 + kt * 32 + c);
            }
        } else {
            // A tile 128x32 fp16 = 512 chunks, 2/thread (R10 exact)
            #pragma unroll
            for (int i = 0; i < 2; ++i) {
                int idx = tid + i * 256;
                int r = idx >> 2, c = (idx & 3) << 3;   // c in halves
                CP16(as + (uint32_t)(r * P::ASTR * 4 + c * 2),
                     Af16 + (size_t)(m0 + r) * 1024 + kt * 32 + c);
            }
        }
        // B tile 128x32 fp16 (W^T rows) = 512 chunks, 2/thread (R10 exact)
        #pragma unroll
        for (int i = 0; i < 2; ++i) {
            int idx = tid + i * 256;
            int r = idx >> 2, c = (idx & 3) << 3;       // c in halves
            CP16(bs + (uint32_t)(r * B_STR * 4 + c * 2),
                 Wg + (size_t)r * 1024 + kt * 32 + c);
        }
    };

    #pragma unroll
    for (int s = 0; s < P::NSTG - 1; ++s) { load_stage(s, s); CP_COMMIT(); }

    int st = 0;
    for (int kt = 0; kt < 32; ++kt) {
        if (AF32) CP_WAIT1(); else CP_WAIT2();
        __syncthreads();

        if (kt + P::NSTG - 1 < 32) {
            int sn = st + P::NSTG - 1; if (sn >= P::NSTG) sn -= P::NSTG;
            load_stage(sn, kt + P::NSTG - 1);
        }
        CP_COMMIT();

        const char* stg = smraw + st * P::STAGE;
        const uint32_t* b32 = (const uint32_t*)(stg + P::AW * 4);

        #pragma unroll
        for (int k16 = 0; k16 < 2; ++k16) {
            uint32_t a[4][4], b[4][2];
            if (AF32) {
                const float* aF = (const float*)stg;
                #pragma unroll
                for (int i = 0; i < 4; ++i) {
                    const float* ap = aF + (wm * 64 + i * 16 + gid) * P::ASTR
                                         + k16 * 16 + 2 * tig;
                    float2 v0 = *(const float2*)ap;
                    float2 v1 = *(const float2*)(ap + 8 * P::ASTR);
                    float2 v2 = *(const float2*)(ap + 8);
                    float2 v3 = *(const float2*)(ap + 8 * P::ASTR + 8);
                    a[i][0] = pack_f16x2(v0.x, v0.y);
                    a[i][1] = pack_f16x2(v1.x, v1.y);
                    a[i][2] = pack_f16x2(v2.x, v2.y);
                    a[i][3] = pack_f16x2(v3.x, v3.y);
                }
            } else {
                const uint32_t* a32 = (const uint32_t*)stg;
                #pragma unroll
                for (int i = 0; i < 4; ++i) {
                    const uint32_t* ap = a32 + (wm * 64 + i * 16 + gid) * P::ASTR
                                             + k16 * 8 + tig;
                    a[i][0] = ap[0];
                    a[i][1] = ap[8 * P::ASTR];
                    a[i][2] = ap[4];
                    a[i][3] = ap[8 * P::ASTR + 4];
                }
            }
            #pragma unroll
            for (int j = 0; j < 4; ++j) {
                const uint32_t* bp = b32 + (wn * 32 + j * 8 + gid) * B_STR
                                         + k16 * 8 + tig;
                b[j][0] = bp[0];
                b[j][1] = bp[4];
            }
            #pragma unroll
            for (int i = 0; i < 4; ++i)
                #pragma unroll
                for (int j = 0; j < 4; ++j)
                    mma_f16(acc[i][j], a[i], b[j]);
        }
        ++st; if (st >= P::NSTG) st -= P::NSTG;
    }
    CP_WAIT0();

    #pragma unroll
    for (int i = 0; i < 4; ++i) {
        const int row = m0 + wm * 64 + i * 16 + gid;
        #pragma unroll
        for (int j = 0; j < 4; ++j) {
            const int col = n0 + wn * 32 + j * 8 + (tig << 1);
            const float b0 = bias[col], b1 = bias[col + 1];
            float v00 = (acc[i][j][0] + b0) * scale;
            float v01 = (acc[i][j][1] + b1) * scale;
            float v10 = (acc[i][j][2] + b0) * scale;
            float v11 = (acc[i][j][3] + b1) * scale;
            if (outHalf) {
                *(uint32_t*)(Ch + (size_t)row * 1024 + col)       = pack_f16x2(v00, v01);
                *(uint32_t*)(Ch + (size_t)(row + 8) * 1024 + col) = pack_f16x2(v10, v11);
            } else {
                *(float2*)(Cf + (size_t)row * 1024 + col)       = make_float2(v00, v01);
                *(float2*)(Cf + (size_t)(row + 8) * 1024 + col) = make_float2(v10, v11);
            }
        }
    }
}

// Merged QKV (A = raw fp32 x converted in-flight; B = fp16 W^T)
__global__ void __launch_bounds__(256, 2)
gemm_qkv(const float* __restrict__ x,
         const __half* __restrict__ wq, const __half* __restrict__ wk,
         const __half* __restrict__ wv,
         const float* __restrict__ bq, const float* __restrict__ bk,
         const float* __restrict__ bv,
         __half* __restrict__ qh, __half* __restrict__ kh,
         float* __restrict__ vf)
{
    extern __shared__ char smraw[];
    const int z = blockIdx.z;
    const __half* Wt  = (z == 0) ? wq : (z == 1) ? wk : wv;
    const float*  bia = (z == 0) ? bq : (z == 1) ? bk : bv;
    if (z == 2)
        gemm_body<true>(smraw, x, Wt, bia, vf, nullptr, 1.0f, 0,
                        blockIdx.x, blockIdx.y);
    else
        gemm_body<true>(smraw, x, Wt, bia, nullptr, (z == 0) ? qh : kh,
                        (z == 0) ? 0.125f : 1.0f, 1, blockIdx.x, blockIdx.y);
}

// Output projection (A = fp16 ctx, B = fp16 Wo^T, fp32 out) — R10 exact path
__global__ void __launch_bounds__(256, 2)
gemm_out(const __half* __restrict__ A, const __half* __restrict__ Wt,
         const float* __restrict__ bias, float* __restrict__ Cf)
{
    extern __shared__ char smraw[];
    gemm_body<false>(smraw, A, Wt, bias, Cf, nullptr, 1.0f, 0,
                     blockIdx.x, blockIdx.y);
}

// ============================================================================
// FP16 flash attention (unchanged — proven, tensor-bound at ~96% of ceiling).
// ============================================================================
#define FQ 128
#define QK_STR 36
#define VS_STR 68
#define VT_STR 36
#define FL_SMEM (128*QK_STR*4 + 2*64*QK_STR*4 + 64*VS_STR*4 + 64*VT_STR*4)

__global__ void __launch_bounds__(256, 2)
flash_tc(const __half* __restrict__ Q, const __half* __restrict__ K,
         const float* __restrict__ V, __half* __restrict__ O)
{
    extern __shared__ char smraw[];
    uint32_t* Qs32 = (uint32_t*)smraw;
    uint32_t* Ks32 = Qs32 + 128 * QK_STR;
    float*    Vs   = (float*)(Ks32 + 2 * 64 * QK_STR);
    uint32_t* Vt   = (uint32_t*)(Vs + 64 * VS_STR);

    const uint32_t smb    = smem_u32(smraw);
    const uint32_t ks_smb = smb + 128 * QK_STR * 4;
    const uint32_t vs_smb = ks_smb + 2 * 64 * QK_STR * 4;
    const uint32_t vt_smb = vs_smb + 64 * VS_STR * 4;

    const int tid  = threadIdx.x;
    const int w    = tid >> 5;
    const int lane = tid & 31;
    const int gid  = lane >> 2;
    const int tig  = lane & 3;
    const int bh   = blockIdx.y;
    const int b    = bh >> 4;
    const int h    = bh & 15;
    const int q0   = blockIdx.x * FQ;

    const __half* Qg = Q + ((size_t)b * SS + q0) * NHEAD + h * HDIM;
    const __half* Kg = K + (size_t)b * SS * NHEAD + h * HDIM;
    const float*  Vg = V + (size_t)b * SS * NHEAD + h * HDIM;

    auto load_k = [&](uint32_t dstbase, const __half* src) {
        #pragma unroll
        for (int i = 0; i < 2; ++i) {
            int idx = tid + i * 256;
            int r = idx >> 3, c = (idx & 7) << 3;
            CP16(dstbase + (uint32_t)(r * QK_STR * 4 + c * 2),
                 src + (size_t)r * NHEAD + c);
        }
    };
    auto load_v = [&](const float* src) {
        #pragma unroll
        for (int i = 0; i < 4; ++i) {
            int idx = tid + i * 256;
            int r = idx >> 4, c = (idx & 15) << 2;
            CP16(vs_smb + (uint32_t)(r * VS_STR + c) * 4,
                 src + (size_t)r * NHEAD + c);
        }
    };

    load_k(ks_smb, Kg);
    load_v(Vg);
    CP_COMMIT();

    #pragma unroll
    for (int i = 0; i < 4; ++i) {
        int idx = tid + i * 256;
        int r = idx >> 3, c8 = idx & 7;
        uint4 t = *(const uint4*)(Qg + (size_t)r * NHEAD + c8 * 8);
        *(uint4*)(Qs32 + r * QK_STR + c8 * 4) = t;
    }

    float m_[2] = {-1e30f, -1e30f};
    float l_[2] = {0.f, 0.f};
    float o[8][4];
    #pragma unroll
    for (int nt = 0; nt < 8; ++nt)
        #pragma unroll
        for (int r = 0; r < 4; ++r) o[nt][r] = 0.f;

    const int qr = w * 16 + gid;
    const int jp = 4 * w + tig;

    const int arow = w * 16 + (lane & 7) + (((lane >> 3) & 1) << 3);
    const uint32_t q_lm = smb + (uint32_t)(arow * QK_STR) * 4
                              + (((lane >> 4) & 1) << 4);
    const int brow = (lane & 7) + (((lane >> 4) & 1) << 3);
    const uint32_t bcol = (((lane >> 3) & 1) << 4);
    const uint32_t k_lm0 = ks_smb + (uint32_t)(brow * QK_STR) * 4 + bcol;
    const uint32_t v_lm  = vt_smb + (uint32_t)(brow * VT_STR) * 4 + bcol;

    for (int it = 0; it < 32; ++it) {
        const int t0 = it * 64;
        CP_WAIT0();
        __syncthreads();

        #pragma unroll
        for (int itd = 0; itd < 8; ++itd) {
            int d = gid + 8 * itd;
            float lo = Vs[(2 * jp)     * VS_STR + d];
            float hi = Vs[(2 * jp + 1) * VS_STR + d];
            Vt[d * VT_STR + jp] = pack_f16x2(lo, hi);
        }
        __syncthreads();

        if (it + 1 < 32) {
            load_k(ks_smb + (uint32_t)(((it + 1) & 1) * 64 * QK_STR) * 4,
                   Kg + (size_t)(t0 + 64) * NHEAD);
            load_v(Vg + (size_t)(t0 + 64) * NHEAD);
        }
        CP_COMMIT();

        const uint32_t klm = k_lm0 + (uint32_t)((it & 1) * 64 * QK_STR) * 4;

        float s[8][4];
        #pragma unroll
        for (int nt = 0; nt < 8; ++nt)
            #pragma unroll
            for (int r = 0; r < 4; ++r) s[nt][r] = 0.f;

        #pragma unroll
        for (int ks = 0; ks < 4; ++ks) {
            uint32_t a[4];
            ldm_x4(a, q_lm + ks * 32);
            #pragma unroll
            for (int p = 0; p < 4; ++p) {
                uint32_t kb[4];
                ldm_x4(kb, klm + (uint32_t)(p * 16 * QK_STR) * 4 + ks * 32);
                mma_f16(s[2 * p],     a, kb);
                mma_f16(s[2 * p + 1], a, kb + 2);
            }
        }

        #pragma unroll
        for (int hh = 0; hh < 2; ++hh) {
            const int c0 = 2 * hh, c1 = c0 + 1;
            float mt = fmaxf(s[0][c0], s[0][c1]);
            #pragma unroll
            for (int nt = 1; nt < 8; ++nt)
                mt = fmaxf(mt, fmaxf(s[nt][c0], s[nt][c1]));
            mt = fmaxf(mt, __shfl_xor_sync(0xffffffffu, mt, 1));
            mt = fmaxf(mt, __shfl_xor_sync(0xffffffffu, mt, 2));
            float mnew = fmaxf(m_[hh], mt);
            float corr = __expf(m_[hh] - mnew);
            m_[hh] = mnew;
            float ls = 0.f;
            #pragma unroll
            for (int nt = 0; nt < 8; ++nt) {
                s[nt][c0] = __expf(s[nt][c0] - mnew);
                s[nt][c1] = __expf(s[nt][c1] - mnew);
                ls += s[nt][c0] + s[nt][c1];
            }
            ls += __shfl_xor_sync(0xffffffffu, ls, 1);
            ls += __shfl_xor_sync(0xffffffffu, ls, 2);
            l_[hh] = l_[hh] * corr + ls;
            #pragma unroll
            for (int nt = 0; nt < 8; ++nt) {
                o[nt][c0] *= corr;
                o[nt][c1] *= corr;
            }
        }

        uint32_t pa[4][4];
        #pragma unroll
        for (int kc = 0; kc < 4; ++kc) {
            pa[kc][0] = pack_f16x2(s[2 * kc][0],     s[2 * kc][1]);
            pa[kc][1] = pack_f16x2(s[2 * kc][2],     s[2 * kc][3]);
            pa[kc][2] = pack_f16x2(s[2 * kc + 1][0], s[2 * kc + 1][1]);
            pa[kc][3] = pack_f16x2(s[2 * kc + 1][2], s[2 * kc + 1][3]);
        }

        #pragma unroll
        for (int kc = 0; kc < 4; ++kc) {
            #pragma unroll
            for (int p = 0; p < 4; ++p) {
                uint32_t vb[4];
                ldm_x4(vb, v_lm + (uint32_t)(p * 16 * VT_STR) * 4 + kc * 32);
                mma_f16(o[2 * p],     pa[kc], vb);
                mma_f16(o[2 * p + 1], pa[kc], vb + 2);
            }
        }
    }

    const float inv0 = 1.f / l_[0];
    const float inv1 = 1.f / l_[1];
    __half* Og = O + ((size_t)b * SS + q0 + qr) * NHEAD + h * HDIM;
    #pragma unroll
    for (int nt = 0; nt < 8; ++nt) {
        *(uint32_t*)(Og + nt * 8 + 2 * tig) =
            pack_f16x2(o[nt][0] * inv0, o[nt][1] * inv0);
        *(uint32_t*)(Og + (size_t)8 * NHEAD + nt * 8 + 2 * tig) =
            pack_f16x2(o[nt][2] * inv1, o[nt][3] * inv1);
    }
}

// ============================================================================
extern "C" void kernel_launch(void* const* d_in, const int* in_sizes, int n_in,
                              void* d_out, int out_size)
{
    (void)in_sizes; (void)n_in; (void)out_size;
    const float* x  = (const float*)d_in[0];
    const float* Wq = (const float*)d_in[1];
    const float* bq = (const float*)d_in[2];
    const float* Wk = (const float*)d_in[3];
    const float* bk = (const float*)d_in[4];
    const float* Wv = (const float*)d_in[5];
    const float* bv = (const float*)d_in[6];
    const float* Wo = (const float*)d_in[7];
    const float* bo = (const float*)d_in[8];
    float* out = (float*)d_out;

    __half *wt, *qh, *kh, *ctxh;
    float  *vp;
    cudaGetSymbolAddress((void**)&wt,   g_wt);
    cudaGetSymbolAddress((void**)&qh,   g_qh);
    cudaGetSymbolAddress((void**)&kh,   g_kh);
    cudaGetSymbolAddress((void**)&vp,   g_v);
    cudaGetSymbolAddress((void**)&ctxh, g_ctxh);
    __half* wqt = wt;
    __half* wkt = wt + (size_t)DD * NHEAD;
    __half* wvt = wt + 2 * (size_t)DD * NHEAD;
    __half* wot = wt + 3 * (size_t)DD * NHEAD;

    cudaFuncSetAttribute(gemm_qkv,
                         cudaFuncAttributeMaxDynamicSharedMemorySize, GP<true>::SMEM);
    cudaFuncSetAttribute(gemm_out,
                         cudaFuncAttributeMaxDynamicSharedMemorySize, GP<false>::SMEM);
    cudaFuncSetAttribute(flash_tc,
                         cudaFuncAttributeMaxDynamicSharedMemorySize, FL_SMEM);

    // Prepass: W transposes only (x converted in-flight by gemm_qkv)
    prepass<<<4096, 256>>>(Wq, Wk, Wv, Wo, wt);

    // Merged QKV projections from raw fp32 x
    dim3 qkvgrid(NHEAD / 128, MROWS / 128, 3);  // (8, 64, 3) = 1536 CTAs
    gemm_qkv<<<qkvgrid, 256, GP<true>::SMEM>>>(x, wqt, wkt, wvt, bq, bk, bv,
                                               qh, kh, vp);

    // FP16 flash attention; ctx out fp16
    flash_tc<<<dim3(SS / FQ, BB * HH), 256, FL_SMEM>>>(qh, kh, vp, ctxh);

    // Output projection (fp32 out)
    dim3 ggrid(NHEAD / 128, MROWS / 128);
    gemm_out<<<ggrid, 256, GP<false>::SMEM>>>(ctxh, wot, bo, out);
}

// round 13
// speedup vs baseline: 1.3526x; 1.0942x over previous
#include <cuda_runtime.h>
#include <cuda_fp16.h>
#include <cstdint>
#include <math.h>

// ============================================================================
// Problem constants
// ============================================================================
#define BB 4
#define SS 2048
#define DD 1024
#define HH 16
#define HDIM 64
#define MROWS (BB * SS)     /* 8192 */
#define NHEAD (HH * HDIM)   /* 1024 */

// Scratch (device globals: allocation-free)
__device__ __align__(16) __half g_xh[MROWS * DD];        // fp16 x
__device__ __align__(16) __half g_wt[4][DD * NHEAD];     // fp16 W^T (q,k,v,o)
__device__ __align__(16) __half g_qh[MROWS * NHEAD];     // fp16 q
__device__ __align__(16) __half g_kh[MROWS * NHEAD];     // fp16 k
__device__ __align__(16) __half g_vh[MROWS * NHEAD];     // fp16 v
__device__ __align__(16) __half g_ctxh[MROWS * NHEAD];   // fp16 ctx

// ============================================================================
// Helpers
// ============================================================================
__device__ __forceinline__ uint32_t smem_u32(const void* p) {
    uint32_t a;
    asm("{ .reg .u64 t; cvta.to.shared.u64 t, %1; cvt.u32.u64 %0, t; }"
        : "=r"(a) : "l"(p));
    return a;
}

__device__ __forceinline__ uint32_t pack_f16x2(float lo, float hi) {
    uint32_t r;
    asm("cvt.rn.f16x2.f32 %0, %1, %2;" : "=r"(r) : "f"(hi), "f"(lo));
    return r;
}

__device__ __forceinline__ void mma_f16(float* c, const uint32_t* a, const uint32_t* b) {
    asm volatile(
        "mma.sync.aligned.m16n8k16.row.col.f32.f16.f16.f32 "
        "{%0,%1,%2,%3}, {%4,%5,%6,%7}, {%8,%9}, {%0,%1,%2,%3};"
        : "+f"(c[0]), "+f"(c[1]), "+f"(c[2]), "+f"(c[3])
        : "r"(a[0]), "r"(a[1]), "r"(a[2]), "r"(a[3]), "r"(b[0]), "r"(b[1]));
}

__device__ __forceinline__ void ldm_x4(uint32_t* r, uint32_t addr) {
    asm volatile(
        "ldmatrix.sync.aligned.m8n8.x4.shared.b16 {%0,%1,%2,%3}, [%4];"
        : "=r"(r[0]), "=r"(r[1]), "=r"(r[2]), "=r"(r[3]) : "r"(addr));
}

// transposed variant: memory [k][n] row-major -> col-major B fragment
__device__ __forceinline__ void ldm_x4_t(uint32_t* r, uint32_t addr) {
    asm volatile(
        "ldmatrix.sync.aligned.m8n8.x4.trans.shared.b16 {%0,%1,%2,%3}, [%4];"
        : "=r"(r[0]), "=r"(r[1]), "=r"(r[2]), "=r"(r[3]) : "r"(addr));
}

#define CP16(dst, src) \
    asm volatile("cp.async.cg.shared.global [%0], [%1], 16;" \
        :: "r"(dst), "l"(src) : "memory")
#define CP_COMMIT() asm volatile("cp.async.commit_group;" ::: "memory")
#define CP_WAIT2()  asm volatile("cp.async.wait_group 2;" ::: "memory")
#define CP_WAIT0()  asm volatile("cp.async.wait_group 0;" ::: "memory")

// ============================================================================
// Merged prepass (single launch) — R10 exact:
//   blocks [0, 8192)        : x fp32 -> fp16 flat
//   blocks [8192, 8192+4096): W{q,k,v,o} fp32 -> fp16 transposed
// ============================================================================
__global__ void __launch_bounds__(256)
prepass(const float* __restrict__ x, __half* __restrict__ xh,
        const float* __restrict__ Wq, const float* __restrict__ Wk,
        const float* __restrict__ Wv, const float* __restrict__ Wo,
        __half* __restrict__ wt)
{
    __shared__ float tbuf[32][33];
    int bid = blockIdx.x;
    if (bid < 8192) {
        int i = bid * 256 + threadIdx.x;
        float4 v = ((const float4*)x)[i];
        uint2 o;
        o.x = pack_f16x2(v.x, v.y);
        o.y = pack_f16x2(v.z, v.w);
        ((uint2*)xh)[i] = o;
        return;
    }
    bid -= 8192;
    const int wsel = bid >> 10;
    const int t    = bid & 1023;
    const float* W = (wsel == 0) ? Wq : (wsel == 1) ? Wk : (wsel == 2) ? Wv : Wo;
    __half* Wt = wt + (size_t)wsel * DD * NHEAD;

    const int bx = (t & 31) * 32, by = (t >> 5) * 32;
    const int tx = threadIdx.x & 31, ty = threadIdx.x >> 5;
    const int xc = bx + tx;
    #pragma unroll
    for (int i = 0; i < 32; i += 8)
        tbuf[ty + i][tx] = W[(size_t)(by + ty + i) * 1024 + xc];
    __syncthreads();
    const int xo = by + tx;
    #pragma unroll
    for (int i = 0; i < 32; i += 8)
        Wt[(size_t)(bx + ty + i) * 1024 + xo] =
            __float2half(tbuf[tx][ty + i]);
}

// ============================================================================
// FP16 GEMM core (R10 exact): CTA 128x128, BK=32, 8 warps, m16n8k16, 4 stages.
// ============================================================================
#define GBM 128
#define GBN 128
#define G_STR 20
#define G_AWORDS (GBM * G_STR)
#define G_STAGE_BYTES (2 * G_AWORDS * 4)
#define G_NSTG 4
#define GSMEM (G_NSTG * G_STAGE_BYTES)

__device__ __forceinline__ void
gemm_body(char* smraw, const __half* __restrict__ A, const __half* __restrict__ Wt,
          const float* __restrict__ bias,
          float* __restrict__ Cf, __half* __restrict__ Ch,
          float scale, int outHalf, int bx, int by)
{
    const uint32_t smb = smem_u32(smraw);

    const int tid  = threadIdx.x;
    const int lane = tid & 31;
    const int wid  = tid >> 5;
    const int wm   = wid & 1;
    const int wn   = wid >> 1;
    const int gid  = lane >> 2;
    const int tig  = lane & 3;
    const int m0   = by * GBM;
    const int n0   = bx * GBN;

    float acc[4][4][4];
    #pragma unroll
    for (int i = 0; i < 4; ++i)
        #pragma unroll
        for (int j = 0; j < 4; ++j)
            #pragma unroll
            for (int r = 0; r < 4; ++r) acc[i][j][r] = 0.f;

    const __half* Ag = A  + (size_t)m0 * 1024;
    const __half* Wg = Wt + (size_t)n0 * 1024;

    auto load_stage = [&](int s, int kt) {
        const uint32_t as = smb + (uint32_t)s * G_STAGE_BYTES;
        const uint32_t bs = as + G_AWORDS * 4;
        #pragma unroll
        for (int i = 0; i < 2; ++i) {
            int idx = tid + i * 256;
            int r = idx >> 2, c = (idx & 3) << 3;
            CP16(as + (uint32_t)(r * G_STR * 4 + c * 2),
                 Ag + (size_t)r * 1024 + kt * 32 + c);
            CP16(bs + (uint32_t)(r * G_STR * 4 + c * 2),
                 Wg + (size_t)r * 1024 + kt * 32 + c);
        }
    };

    #pragma unroll
    for (int s = 0; s < 3; ++s) { load_stage(s, s); CP_COMMIT(); }

    for (int kt = 0; kt < 32; ++kt) {
        CP_WAIT2();
        __syncthreads();

        if (kt + 3 < 32) load_stage((kt + 3) & 3, kt + 3);
        CP_COMMIT();

        const uint32_t* a32 = (const uint32_t*)(smraw + (kt & 3) * G_STAGE_BYTES);
        const uint32_t* b32 = a32 + G_AWORDS;

        #pragma unroll
        for (int k16 = 0; k16 < 2; ++k16) {
            uint32_t a[4][4], b[4][2];
            #pragma unroll
            for (int i = 0; i < 4; ++i) {
                const uint32_t* ap = a32 + (wm * 64 + i * 16 + gid) * G_STR
                                         + k16 * 8 + tig;
                a[i][0] = ap[0];
                a[i][1] = ap[8 * G_STR];
                a[i][2] = ap[4];
                a[i][3] = ap[8 * G_STR + 4];
            }
            #pragma unroll
            for (int j = 0; j < 4; ++j) {
                const uint32_t* bp = b32 + (wn * 32 + j * 8 + gid) * G_STR
                                         + k16 * 8 + tig;
                b[j][0] = bp[0];
                b[j][1] = bp[4];
            }
            #pragma unroll
            for (int i = 0; i < 4; ++i)
                #pragma unroll
                for (int j = 0; j < 4; ++j)
                    mma_f16(acc[i][j], a[i], b[j]);
        }
    }
    CP_WAIT0();

    #pragma unroll
    for (int i = 0; i < 4; ++i) {
        const int row = m0 + wm * 64 + i * 16 + gid;
        #pragma unroll
        for (int j = 0; j < 4; ++j) {
            const int col = n0 + wn * 32 + j * 8 + (tig << 1);
            const float b0 = bias[col], b1 = bias[col + 1];
            float v00 = (acc[i][j][0] + b0) * scale;
            float v01 = (acc[i][j][1] + b1) * scale;
            float v10 = (acc[i][j][2] + b0) * scale;
            float v11 = (acc[i][j][3] + b1) * scale;
            if (outHalf) {
                *(uint32_t*)(Ch + (size_t)row * 1024 + col)       = pack_f16x2(v00, v01);
                *(uint32_t*)(Ch + (size_t)(row + 8) * 1024 + col) = pack_f16x2(v10, v11);
            } else {
                *(float2*)(Cf + (size_t)row * 1024 + col)       = make_float2(v00, v01);
                *(float2*)(Cf + (size_t)(row + 8) * 1024 + col) = make_float2(v10, v11);
            }
        }
    }
}

// Merged QKV: blockIdx.z selects {q, k, v}; ALL outputs fp16 now
// (v's single cvt.rn moved here from the former flash transpose — same value)
__global__ void __launch_bounds__(256, 2)
gemm_qkv(const __half* __restrict__ xh,
         const __half* __restrict__ wq, const __half* __restrict__ wk,
         const __half* __restrict__ wv,
         const float* __restrict__ bq, const float* __restrict__ bk,
         const float* __restrict__ bv,
         __half* __restrict__ qh, __half* __restrict__ kh,
         __half* __restrict__ vh)
{
    extern __shared__ char smraw[];
    const int z = blockIdx.z;
    const __half* Wt  = (z == 0) ? wq : (z == 1) ? wk : wv;
    const float*  bia = (z == 0) ? bq : (z == 1) ? bk : bv;
    __half* outp      = (z == 0) ? qh : (z == 1) ? kh : vh;
    const float scale = (z == 0) ? 0.125f : 1.0f;
    gemm_body(smraw, xh, Wt, bia, nullptr, outp, scale, 1,
              blockIdx.x, blockIdx.y);
}

// Output projection (fp32 out) — R10 exact
__global__ void __launch_bounds__(256, 2)
gemm_f16(const __half* __restrict__ A, const __half* __restrict__ Wt,
         const float* __restrict__ bias, float* __restrict__ Cf, float scale)
{
    extern __shared__ char smraw[];
    gemm_body(smraw, A, Wt, bias, Cf, nullptr, scale, 0,
              blockIdx.x, blockIdx.y);
}

// ============================================================================
// FP16 flash attention — V transpose phase ELIMINATED via ldmatrix.trans.
// Q, K, V all fp16, stride 36 words. K and V double-buffered via cp.async.
// One barrier per iteration.
// ============================================================================
#define FQ 128
#define QK_STR 36
// Qs 128x36 + Ks 2x64x36 + Vs 2x64x36 (uint32 words)
#define FL_SMEM ((128*QK_STR + 2*64*QK_STR + 2*64*QK_STR) * 4)  /* 55296 */

__global__ void __launch_bounds__(256, 2)
flash_tc(const __half* __restrict__ Q, const __half* __restrict__ K,
         const __half* __restrict__ V, __half* __restrict__ O)
{
    extern __shared__ char smraw[];
    const uint32_t smb    = smem_u32(smraw);
    const uint32_t ks_smb = smb + 128 * QK_STR * 4;
    const uint32_t vs_smb = ks_smb + 2 * 64 * QK_STR * 4;
    uint32_t* Qs32 = (uint32_t*)smraw;

    const int tid  = threadIdx.x;
    const int w    = tid >> 5;
    const int lane = tid & 31;
    const int gid  = lane >> 2;
    const int tig  = lane & 3;
    const int bh   = blockIdx.y;
    const int b    = bh >> 4;
    const int h    = bh & 15;
    const int q0   = blockIdx.x * FQ;

    const __half* Qg = Q + ((size_t)b * SS + q0) * NHEAD + h * HDIM;
    const __half* Kg = K + (size_t)b * SS * NHEAD + h * HDIM;
    const __half* Vg = V + (size_t)b * SS * NHEAD + h * HDIM;

    // fp16 64x64 tile = 8KB = 512 chunks = 2/thread (proven K loader)
    auto load_tile = [&](uint32_t dstbase, const __half* src) {
        #pragma unroll
        for (int i = 0; i < 2; ++i) {
            int idx = tid + i * 256;
            int r = idx >> 3, c = (idx & 7) << 3;
            CP16(dstbase + (uint32_t)(r * QK_STR * 4 + c * 2),
                 src + (size_t)r * NHEAD + c);
        }
    };

    // Prologue: K(0), V(0) -> buffer 0
    load_tile(ks_smb, Kg);
    load_tile(vs_smb, Vg);
    CP_COMMIT();

    // Load Q tile (128 x 64 fp16) while DMA flies
    #pragma unroll
    for (int i = 0; i < 4; ++i) {
        int idx = tid + i * 256;
        int r = idx >> 3, c8 = idx & 7;
        uint4 t = *(const uint4*)(Qg + (size_t)r * NHEAD + c8 * 8);
        *(uint4*)(Qs32 + r * QK_STR + c8 * 4) = t;
    }

    float m_[2] = {-1e30f, -1e30f};
    float l_[2] = {0.f, 0.f};
    float o[8][4];
    #pragma unroll
    for (int nt = 0; nt < 8; ++nt)
        #pragma unroll
        for (int r = 0; r < 4; ++r) o[nt][r] = 0.f;

    const int qr = w * 16 + gid;

    // A-frag (Q) ldmatrix addresses (proven)
    const int arow = w * 16 + (lane & 7) + (((lane >> 3) & 1) << 3);
    const uint32_t q_lm = smb + (uint32_t)(arow * QK_STR) * 4
                              + (((lane >> 4) & 1) << 4);
    // B-frag (K, non-trans; memory [n][k]) — proven mapping
    const int brow = (lane & 7) + (((lane >> 4) & 1) << 3);
    const uint32_t bcol = (((lane >> 3) & 1) << 4);
    const uint32_t k_lm0 = ks_smb + (uint32_t)(brow * QK_STR) * 4 + bcol;
    // B-frag (V, TRANS; memory [k][n]) — same mapping, selector bits swapped:
    //   row = k within 16-chunk (lane>>3 picks k-high), col = n16 (lane>>4)
    const int vrow = (lane & 7) + (((lane >> 3) & 1) << 3);
    const uint32_t vcol = (((lane >> 4) & 1) << 4);
    const uint32_t v_lm0 = vs_smb + (uint32_t)(vrow * QK_STR) * 4 + vcol;

    for (int it = 0; it < 32; ++it) {
        const int t0 = it * 64;
        CP_WAIT0();          // K(it), V(it) arrived
        __syncthreads();     // visible to all; prev-iter reads of alt buf done

        // Prefetch next K,V into alternate buffers
        if (it + 1 < 32) {
            const uint32_t alt = (uint32_t)(((it + 1) & 1) * 64 * QK_STR) * 4;
            load_tile(ks_smb + alt, Kg + (size_t)(t0 + 64) * NHEAD);
            load_tile(vs_smb + alt, Vg + (size_t)(t0 + 64) * NHEAD);
        }
        CP_COMMIT();

        const uint32_t cur = (uint32_t)((it & 1) * 64 * QK_STR) * 4;
        const uint32_t klm = k_lm0 + cur;
        const uint32_t vlm = v_lm0 + cur;

        // S = Q K^T (fp16 mma, ldmatrix frags)
        float s[8][4];
        #pragma unroll
        for (int nt = 0; nt < 8; ++nt)
            #pragma unroll
            for (int r = 0; r < 4; ++r) s[nt][r] = 0.f;

        #pragma unroll
        for (int ks = 0; ks < 4; ++ks) {
            uint32_t a[4];
            ldm_x4(a, q_lm + ks * 32);
            #pragma unroll
            for (int p = 0; p < 4; ++p) {
                uint32_t kb[4];
                ldm_x4(kb, klm + (uint32_t)(p * 16 * QK_STR) * 4 + ks * 32);
                mma_f16(s[2 * p],     a, kb);
                mma_f16(s[2 * p + 1], a, kb + 2);
            }
        }

        // Online softmax per row-half
        #pragma unroll
        for (int hh = 0; hh < 2; ++hh) {
            const int c0 = 2 * hh, c1 = c0 + 1;
            float mt = fmaxf(s[0][c0], s[0][c1]);
            #pragma unroll
            for (int nt = 1; nt < 8; ++nt)
                mt = fmaxf(mt, fmaxf(s[nt][c0], s[nt][c1]));
            mt = fmaxf(mt, __shfl_xor_sync(0xffffffffu, mt, 1));
            mt = fmaxf(mt, __shfl_xor_sync(0xffffffffu, mt, 2));
            float mnew = fmaxf(m_[hh], mt);
            float corr = __expf(m_[hh] - mnew);
            m_[hh] = mnew;
            float ls = 0.f;
            #pragma unroll
            for (int nt = 0; nt < 8; ++nt) {
                s[nt][c0] = __expf(s[nt][c0] - mnew);
                s[nt][c1] = __expf(s[nt][c1] - mnew);
                ls += s[nt][c0] + s[nt][c1];
            }
            ls += __shfl_xor_sync(0xffffffffu, ls, 1);
            ls += __shfl_xor_sync(0xffffffffu, ls, 2);
            l_[hh] = l_[hh] * corr + ls;
            #pragma unroll
            for (int nt = 0; nt < 8; ++nt) {
                o[nt][c0] *= corr;
                o[nt][c1] *= corr;
            }
        }

        // Pack P: S C-frag -> fp16 A-frag (registers only)
        uint32_t pa[4][4];
        #pragma unroll
        for (int kc = 0; kc < 4; ++kc) {
            pa[kc][0] = pack_f16x2(s[2 * kc][0],     s[2 * kc][1]);
            pa[kc][1] = pack_f16x2(s[2 * kc][2],     s[2 * kc][3]);
            pa[kc][2] = pack_f16x2(s[2 * kc + 1][0], s[2 * kc + 1][1]);
            pa[kc][3] = pack_f16x2(s[2 * kc + 1][2], s[2 * kc + 1][3]);
        }

        // O += P V (fp16 mma, ldmatrix.trans B-frags from natural V)
        #pragma unroll
        for (int kc = 0; kc < 4; ++kc) {
            #pragma unroll
            for (int p = 0; p < 4; ++p) {
                uint32_t vb[4];
                ldm_x4_t(vb, vlm + (uint32_t)(kc * 16 * QK_STR) * 4 + p * 32);
                mma_f16(o[2 * p],     pa[kc], vb);
                mma_f16(o[2 * p + 1], pa[kc], vb + 2);
            }
        }
    }

    const float inv0 = 1.f / l_[0];
    const float inv1 = 1.f / l_[1];
    __half* Og = O + ((size_t)b * SS + q0 + qr) * NHEAD + h * HDIM;
    #pragma unroll
    for (int nt = 0; nt < 8; ++nt) {
        *(uint32_t*)(Og + nt * 8 + 2 * tig) =
            pack_f16x2(o[nt][0] * inv0, o[nt][1] * inv0);
        *(uint32_t*)(Og + (size_t)8 * NHEAD + nt * 8 + 2 * tig) =
            pack_f16x2(o[nt][2] * inv1, o[nt][3] * inv1);
    }
}

// ============================================================================
extern "C" void kernel_launch(void* const* d_in, const int* in_sizes, int n_in,
                              void* d_out, int out_size)
{
    (void)in_sizes; (void)n_in; (void)out_size;
    const float* x  = (const float*)d_in[0];
    const float* Wq = (const float*)d_in[1];
    const float* bq = (const float*)d_in[2];
    const float* Wk = (const float*)d_in[3];
    const float* bk = (const float*)d_in[4];
    const float* Wv = (const float*)d_in[5];
    const float* bv = (const float*)d_in[6];
    const float* Wo = (const float*)d_in[7];
    const float* bo = (const float*)d_in[8];
    float* out = (float*)d_out;

    __half *xh, *wt, *qh, *kh, *vh, *ctxh;
    cudaGetSymbolAddress((void**)&xh,   g_xh);
    cudaGetSymbolAddress((void**)&wt,   g_wt);
    cudaGetSymbolAddress((void**)&qh,   g_qh);
    cudaGetSymbolAddress((void**)&kh,   g_kh);
    cudaGetSymbolAddress((void**)&vh,   g_vh);
    cudaGetSymbolAddress((void**)&ctxh, g_ctxh);
    __half* wqt = wt;
    __half* wkt = wt + (size_t)DD * NHEAD;
    __half* wvt = wt + 2 * (size_t)DD * NHEAD;
    __half* wot = wt + 3 * (size_t)DD * NHEAD;

    cudaFuncSetAttribute(gemm_qkv,
                         cudaFuncAttributeMaxDynamicSharedMemorySize, GSMEM);
    cudaFuncSetAttribute(gemm_f16,
                         cudaFuncAttributeMaxDynamicSharedMemorySize, GSMEM);
    cudaFuncSetAttribute(flash_tc,
                         cudaFuncAttributeMaxDynamicSharedMemorySize, FL_SMEM);

    // Merged prepass: x cvt (8192 blocks) + 4 W transposes (4096 blocks)
    prepass<<<8192 + 4096, 256>>>(x, xh, Wq, Wk, Wv, Wo, wt);

    // Merged QKV projections (128x128 tiles); q,k,v all fp16 out
    dim3 qkvgrid(NHEAD / GBN, MROWS / GBM, 3);  // (8, 64, 3)
    gemm_qkv<<<qkvgrid, 256, GSMEM>>>(xh, wqt, wkt, wvt, bq, bk, bv,
                                      qh, kh, vh);

    // FP16 flash attention (transpose-free PV via ldmatrix.trans)
    flash_tc<<<dim3(SS / FQ, BB * HH), 256, FL_SMEM>>>(qh, kh, vh, ctxh);

    // Output projection (fp32 out)
    dim3 ggrid(NHEAD / GBN, MROWS / GBM);
    gemm_f16<<<ggrid, 256, GSMEM>>>(ctxh, wot, bo, out, 1.0f);
}

// round 14
// speedup vs baseline: 1.4597x; 1.0792x over previous
#include <cuda_runtime.h>
#include <cuda_fp16.h>
#include <cstdint>
#include <math.h>

// ============================================================================
// Problem constants
// ============================================================================
#define BB 4
#define SS 2048
#define DD 1024
#define HH 16
#define HDIM 64
#define MROWS (BB * SS)     /* 8192 */
#define NHEAD (HH * HDIM)   /* 1024 */

// Scratch (device globals: allocation-free)
__device__ __align__(16) __half g_xh[MROWS * DD];        // fp16 x
__device__ __align__(16) __half g_wt[4][DD * NHEAD];     // fp16 W^T (q,k,v,o)
__device__ __align__(16) __half g_qh[MROWS * NHEAD];     // fp16 q
__device__ __align__(16) __half g_kh[MROWS * NHEAD];     // fp16 k
__device__ __align__(16) __half g_vh[MROWS * NHEAD];     // fp16 v
__device__ __align__(16) __half g_ctxh[MROWS * NHEAD];   // fp16 ctx

// ============================================================================
// Helpers
// ============================================================================
__device__ __forceinline__ uint32_t smem_u32(const void* p) {
    uint32_t a;
    asm("{ .reg .u64 t; cvta.to.shared.u64 t, %1; cvt.u32.u64 %0, t; }"
        : "=r"(a) : "l"(p));
    return a;
}

__device__ __forceinline__ uint32_t pack_f16x2(float lo, float hi) {
    uint32_t r;
    asm("cvt.rn.f16x2.f32 %0, %1, %2;" : "=r"(r) : "f"(hi), "f"(lo));
    return r;
}

__device__ __forceinline__ void mma_f16(float* c, const uint32_t* a, const uint32_t* b) {
    asm volatile(
        "mma.sync.aligned.m16n8k16.row.col.f32.f16.f16.f32 "
        "{%0,%1,%2,%3}, {%4,%5,%6,%7}, {%8,%9}, {%0,%1,%2,%3};"
        : "+f"(c[0]), "+f"(c[1]), "+f"(c[2]), "+f"(c[3])
        : "r"(a[0]), "r"(a[1]), "r"(a[2]), "r"(a[3]), "r"(b[0]), "r"(b[1]));
}

__device__ __forceinline__ void ldm_x4(uint32_t* r, uint32_t addr) {
    asm volatile(
        "ldmatrix.sync.aligned.m8n8.x4.shared.b16 {%0,%1,%2,%3}, [%4];"
        : "=r"(r[0]), "=r"(r[1]), "=r"(r[2]), "=r"(r[3]) : "r"(addr));
}

// transposed variant: memory [k][n] row-major -> col-major B fragment
__device__ __forceinline__ void ldm_x4_t(uint32_t* r, uint32_t addr) {
    asm volatile(
        "ldmatrix.sync.aligned.m8n8.x4.trans.shared.b16 {%0,%1,%2,%3}, [%4];"
        : "=r"(r[0]), "=r"(r[1]), "=r"(r[2]), "=r"(r[3]) : "r"(addr));
}

#define CP16(dst, src) \
    asm volatile("cp.async.cg.shared.global [%0], [%1], 16;" \
        :: "r"(dst), "l"(src) : "memory")
#define CP_COMMIT() asm volatile("cp.async.commit_group;" ::: "memory")
#define CP_WAIT1()  asm volatile("cp.async.wait_group 1;" ::: "memory")
#define CP_WAIT0()  asm volatile("cp.async.wait_group 0;" ::: "memory")

// ============================================================================
// Merged prepass (single launch) — R13 exact:
//   blocks [0, 8192)        : x fp32 -> fp16 flat
//   blocks [8192, 8192+4096): W{q,k,v,o} fp32 -> fp16 transposed
// ============================================================================
__global__ void __launch_bounds__(256)
prepass(const float* __restrict__ x, __half* __restrict__ xh,
        const float* __restrict__ Wq, const float* __restrict__ Wk,
        const float* __restrict__ Wv, const float* __restrict__ Wo,
        __half* __restrict__ wt)
{
    __shared__ float tbuf[32][33];
    int bid = blockIdx.x;
    if (bid < 8192) {
        int i = bid * 256 + threadIdx.x;
        float4 v = ((const float4*)x)[i];
        uint2 o;
        o.x = pack_f16x2(v.x, v.y);
        o.y = pack_f16x2(v.z, v.w);
        ((uint2*)xh)[i] = o;
        return;
    }
    bid -= 8192;
    const int wsel = bid >> 10;
    const int t    = bid & 1023;
    const float* W = (wsel == 0) ? Wq : (wsel == 1) ? Wk : (wsel == 2) ? Wv : Wo;
    __half* Wt = wt + (size_t)wsel * DD * NHEAD;

    const int bx = (t & 31) * 32, by = (t >> 5) * 32;
    const int tx = threadIdx.x & 31, ty = threadIdx.x >> 5;
    const int xc = bx + tx;
    #pragma unroll
    for (int i = 0; i < 32; i += 8)
        tbuf[ty + i][tx] = W[(size_t)(by + ty + i) * 1024 + xc];
    __syncthreads();
    const int xo = by + tx;
    #pragma unroll
    for (int i = 0; i < 32; i += 8)
        Wt[(size_t)(bx + ty + i) * 1024 + xo] =
            __float2half(tbuf[tx][ty + i]);
}

// ============================================================================
// FP16 GEMM core — BK=64 (halved per-kt fixed costs vs R13's BK=32).
// CTA 128x128, 8 warps (2Mx4N), warp tile 64x32, m16n8k16, 3 stages.
// K-accumulation order identical to BK=32 -> bit-identical output.
// ============================================================================
#define GBM 128
#define GBN 128
#define G_STR 36   /* b32 words per smem row: 64 halves (32 w) + 4 pad */
#define G_AWORDS (GBM * G_STR)
#define G_STAGE_BYTES (2 * G_AWORDS * 4)     /* 36864 */
#define G_NSTG 3
#define GSMEM (G_NSTG * G_STAGE_BYTES)       /* 110592 */

__device__ __forceinline__ void
gemm_body(char* smraw, const __half* __restrict__ A, const __half* __restrict__ Wt,
          const float* __restrict__ bias,
          float* __restrict__ Cf, __half* __restrict__ Ch,
          float scale, int outHalf, int bx, int by)
{
    const uint32_t smb = smem_u32(smraw);

    const int tid  = threadIdx.x;
    const int lane = tid & 31;
    const int wid  = tid >> 5;
    const int wm   = wid & 1;
    const int wn   = wid >> 1;
    const int gid  = lane >> 2;
    const int tig  = lane & 3;
    const int m0   = by * GBM;
    const int n0   = bx * GBN;

    float acc[4][4][4];
    #pragma unroll
    for (int i = 0; i < 4; ++i)
        #pragma unroll
        for (int j = 0; j < 4; ++j)
            #pragma unroll
            for (int r = 0; r < 4; ++r) acc[i][j][r] = 0.f;

    const __half* Ag = A  + (size_t)m0 * 1024;
    const __half* Wg = Wt + (size_t)n0 * 1024;

    // Stage: A tile 128x64 fp16 + B tile 128x64 fp16; 1024 chunks each side,
    // 4 chunks/thread/side. Row = 8 chunks of 8 halves.
    auto load_stage = [&](int s, int kt) {
        const uint32_t as = smb + (uint32_t)s * G_STAGE_BYTES;
        const uint32_t bs = as + G_AWORDS * 4;
        #pragma unroll
        for (int i = 0; i < 4; ++i) {
            int idx = tid + i * 256;
            int r = idx >> 3, c = (idx & 7) << 3;   // c in halves
            CP16(as + (uint32_t)(r * G_STR * 4 + c * 2),
                 Ag + (size_t)r * 1024 + kt * 64 + c);
            CP16(bs + (uint32_t)(r * G_STR * 4 + c * 2),
                 Wg + (size_t)r * 1024 + kt * 64 + c);
        }
    };

    load_stage(0, 0); CP_COMMIT();
    load_stage(1, 1); CP_COMMIT();

    int st = 0;
    for (int kt = 0; kt < 16; ++kt) {
        CP_WAIT1();
        __syncthreads();

        if (kt + 2 < 16) {
            int sn = st + 2; if (sn >= 3) sn -= 3;
            load_stage(sn, kt + 2);
        }
        CP_COMMIT();

        const uint32_t* a32 = (const uint32_t*)(smraw + st * G_STAGE_BYTES);
        const uint32_t* b32 = a32 + G_AWORDS;

        #pragma unroll
        for (int k16 = 0; k16 < 4; ++k16) {
            uint32_t a[4][4], b[4][2];
            #pragma unroll
            for (int i = 0; i < 4; ++i) {
                const uint32_t* ap = a32 + (wm * 64 + i * 16 + gid) * G_STR
                                         + k16 * 8 + tig;
                a[i][0] = ap[0];
                a[i][1] = ap[8 * G_STR];
                a[i][2] = ap[4];
                a[i][3] = ap[8 * G_STR + 4];
            }
            #pragma unroll
            for (int j = 0; j < 4; ++j) {
                const uint32_t* bp = b32 + (wn * 32 + j * 8 + gid) * G_STR
                                         + k16 * 8 + tig;
                b[j][0] = bp[0];
                b[j][1] = bp[4];
            }
            #pragma unroll
            for (int i = 0; i < 4; ++i)
                #pragma unroll
                for (int j = 0; j < 4; ++j)
                    mma_f16(acc[i][j], a[i], b[j]);
        }
        ++st; if (st >= 3) st -= 3;
    }
    CP_WAIT0();

    #pragma unroll
    for (int i = 0; i < 4; ++i) {
        const int row = m0 + wm * 64 + i * 16 + gid;
        #pragma unroll
        for (int j = 0; j < 4; ++j) {
            const int col = n0 + wn * 32 + j * 8 + (tig << 1);
            const float b0 = bias[col], b1 = bias[col + 1];
            float v00 = (acc[i][j][0] + b0) * scale;
            float v01 = (acc[i][j][1] + b1) * scale;
            float v10 = (acc[i][j][2] + b0) * scale;
            float v11 = (acc[i][j][3] + b1) * scale;
            if (outHalf) {
                *(uint32_t*)(Ch + (size_t)row * 1024 + col)       = pack_f16x2(v00, v01);
                *(uint32_t*)(Ch + (size_t)(row + 8) * 1024 + col) = pack_f16x2(v10, v11);
            } else {
                *(float2*)(Cf + (size_t)row * 1024 + col)       = make_float2(v00, v01);
                *(float2*)(Cf + (size_t)(row + 8) * 1024 + col) = make_float2(v10, v11);
            }
        }
    }
}

// Merged QKV: blockIdx.z selects {q, k, v}; all outputs fp16
__global__ void __launch_bounds__(256, 2)
gemm_qkv(const __half* __restrict__ xh,
         const __half* __restrict__ wq, const __half* __restrict__ wk,
         const __half* __restrict__ wv,
         const float* __restrict__ bq, const float* __restrict__ bk,
         const float* __restrict__ bv,
         __half* __restrict__ qh, __half* __restrict__ kh,
         __half* __restrict__ vh)
{
    extern __shared__ char smraw[];
    const int z = blockIdx.z;
    const __half* Wt  = (z == 0) ? wq : (z == 1) ? wk : wv;
    const float*  bia = (z == 0) ? bq : (z == 1) ? bk : bv;
    __half* outp      = (z == 0) ? qh : (z == 1) ? kh : vh;
    const float scale = (z == 0) ? 0.125f : 1.0f;
    gemm_body(smraw, xh, Wt, bia, nullptr, outp, scale, 1,
              blockIdx.x, blockIdx.y);
}

// Output projection (fp32 out)
__global__ void __launch_bounds__(256, 2)
gemm_f16(const __half* __restrict__ A, const __half* __restrict__ Wt,
         const float* __restrict__ bias, float* __restrict__ Cf, float scale)
{
    extern __shared__ char smraw[];
    gemm_body(smraw, A, Wt, bias, Cf, nullptr, scale, 0,
              blockIdx.x, blockIdx.y);
}

// ============================================================================
// FP16 flash attention (R13 exact — transpose-free PV via ldmatrix.trans).
// ============================================================================
#define FQ 128
#define QK_STR 36
#define FL_SMEM ((128*QK_STR + 2*64*QK_STR + 2*64*QK_STR) * 4)  /* 55296 */

__global__ void __launch_bounds__(256, 2)
flash_tc(const __half* __restrict__ Q, const __half* __restrict__ K,
         const __half* __restrict__ V, __half* __restrict__ O)
{
    extern __shared__ char smraw[];
    const uint32_t smb    = smem_u32(smraw);
    const uint32_t ks_smb = smb + 128 * QK_STR * 4;
    const uint32_t vs_smb = ks_smb + 2 * 64 * QK_STR * 4;
    uint32_t* Qs32 = (uint32_t*)smraw;

    const int tid  = threadIdx.x;
    const int w    = tid >> 5;
    const int lane = tid & 31;
    const int gid  = lane >> 2;
    const int tig  = lane & 3;
    const int bh   = blockIdx.y;
    const int b    = bh >> 4;
    const int h    = bh & 15;
    const int q0   = blockIdx.x * FQ;

    const __half* Qg = Q + ((size_t)b * SS + q0) * NHEAD + h * HDIM;
    const __half* Kg = K + (size_t)b * SS * NHEAD + h * HDIM;
    const __half* Vg = V + (size_t)b * SS * NHEAD + h * HDIM;

    auto load_tile = [&](uint32_t dstbase, const __half* src) {
        #pragma unroll
        for (int i = 0; i < 2; ++i) {
            int idx = tid + i * 256;
            int r = idx >> 3, c = (idx & 7) << 3;
            CP16(dstbase + (uint32_t)(r * QK_STR * 4 + c * 2),
                 src + (size_t)r * NHEAD + c);
        }
    };

    load_tile(ks_smb, Kg);
    load_tile(vs_smb, Vg);
    CP_COMMIT();

    #pragma unroll
    for (int i = 0; i < 4; ++i) {
        int idx = tid + i * 256;
        int r = idx >> 3, c8 = idx & 7;
        uint4 t = *(const uint4*)(Qg + (size_t)r * NHEAD + c8 * 8);
        *(uint4*)(Qs32 + r * QK_STR + c8 * 4) = t;
    }

    float m_[2] = {-1e30f, -1e30f};
    float l_[2] = {0.f, 0.f};
    float o[8][4];
    #pragma unroll
    for (int nt = 0; nt < 8; ++nt)
        #pragma unroll
        for (int r = 0; r < 4; ++r) o[nt][r] = 0.f;

    const int qr = w * 16 + gid;

    const int arow = w * 16 + (lane & 7) + (((lane >> 3) & 1) << 3);
    const uint32_t q_lm = smb + (uint32_t)(arow * QK_STR) * 4
                              + (((lane >> 4) & 1) << 4);
    const int brow = (lane & 7) + (((lane >> 4) & 1) << 3);
    const uint32_t bcol = (((lane >> 3) & 1) << 4);
    const uint32_t k_lm0 = ks_smb + (uint32_t)(brow * QK_STR) * 4 + bcol;
    const int vrow = (lane & 7) + (((lane >> 3) & 1) << 3);
    const uint32_t vcol = (((lane >> 4) & 1) << 4);
    const uint32_t v_lm0 = vs_smb + (uint32_t)(vrow * QK_STR) * 4 + vcol;

    for (int it = 0; it < 32; ++it) {
        const int t0 = it * 64;
        CP_WAIT0();
        __syncthreads();

        if (it + 1 < 32) {
            const uint32_t alt = (uint32_t)(((it + 1) & 1) * 64 * QK_STR) * 4;
            load_tile(ks_smb + alt, Kg + (size_t)(t0 + 64) * NHEAD);
            load_tile(vs_smb + alt, Vg + (size_t)(t0 + 64) * NHEAD);
        }
        CP_COMMIT();

        const uint32_t cur = (uint32_t)((it & 1) * 64 * QK_STR) * 4;
        const uint32_t klm = k_lm0 + cur;
        const uint32_t vlm = v_lm0 + cur;

        float s[8][4];
        #pragma unroll
        for (int nt = 0; nt < 8; ++nt)
            #pragma unroll
            for (int r = 0; r < 4; ++r) s[nt][r] = 0.f;

        #pragma unroll
        for (int ks = 0; ks < 4; ++ks) {
            uint32_t a[4];
            ldm_x4(a, q_lm + ks * 32);
            #pragma unroll
            for (int p = 0; p < 4; ++p) {
                uint32_t kb[4];
                ldm_x4(kb, klm + (uint32_t)(p * 16 * QK_STR) * 4 + ks * 32);
                mma_f16(s[2 * p],     a, kb);
                mma_f16(s[2 * p + 1], a, kb + 2);
            }
        }

        #pragma unroll
        for (int hh = 0; hh < 2; ++hh) {
            const int c0 = 2 * hh, c1 = c0 + 1;
            float mt = fmaxf(s[0][c0], s[0][c1]);
            #pragma unroll
            for (int nt = 1; nt < 8; ++nt)
                mt = fmaxf(mt, fmaxf(s[nt][c0], s[nt][c1]));
            mt = fmaxf(mt, __shfl_xor_sync(0xffffffffu, mt, 1));
            mt = fmaxf(mt, __shfl_xor_sync(0xffffffffu, mt, 2));
            float mnew = fmaxf(m_[hh], mt);
            float corr = __expf(m_[hh] - mnew);
            m_[hh] = mnew;
            float ls = 0.f;
            #pragma unroll
            for (int nt = 0; nt < 8; ++nt) {
                s[nt][c0] = __expf(s[nt][c0] - mnew);
                s[nt][c1] = __expf(s[nt][c1] - mnew);
                ls += s[nt][c0] + s[nt][c1];
            }
            ls += __shfl_xor_sync(0xffffffffu, ls, 1);
            ls += __shfl_xor_sync(0xffffffffu, ls, 2);
            l_[hh] = l_[hh] * corr + ls;
            #pragma unroll
            for (int nt = 0; nt < 8; ++nt) {
                o[nt][c0] *= corr;
                o[nt][c1] *= corr;
            }
        }

        uint32_t pa[4][4];
        #pragma unroll
        for (int kc = 0; kc < 4; ++kc) {
            pa[kc][0] = pack_f16x2(s[2 * kc][0],     s[2 * kc][1]);
            pa[kc][1] = pack_f16x2(s[2 * kc][2],     s[2 * kc][3]);
            pa[kc][2] = pack_f16x2(s[2 * kc + 1][0], s[2 * kc + 1][1]);
            pa[kc][3] = pack_f16x2(s[2 * kc + 1][2], s[2 * kc + 1][3]);
        }

        #pragma unroll
        for (int kc = 0; kc < 4; ++kc) {
            #pragma unroll
            for (int p = 0; p < 4; ++p) {
                uint32_t vb[4];
                ldm_x4_t(vb, vlm + (uint32_t)(kc * 16 * QK_STR) * 4 + p * 32);
                mma_f16(o[2 * p],     pa[kc], vb);
                mma_f16(o[2 * p + 1], pa[kc], vb + 2);
            }
        }
    }

    const float inv0 = 1.f / l_[0];
    const float inv1 = 1.f / l_[1];
    __half* Og = O + ((size_t)b * SS + q0 + qr) * NHEAD + h * HDIM;
    #pragma unroll
    for (int nt = 0; nt < 8; ++nt) {
        *(uint32_t*)(Og + nt * 8 + 2 * tig) =
            pack_f16x2(o[nt][0] * inv0, o[nt][1] * inv0);
        *(uint32_t*)(Og + (size_t)8 * NHEAD + nt * 8 + 2 * tig) =
            pack_f16x2(o[nt][2] * inv1, o[nt][3] * inv1);
    }
}

// ============================================================================
extern "C" void kernel_launch(void* const* d_in, const int* in_sizes, int n_in,
                              void* d_out, int out_size)
{
    (void)in_sizes; (void)n_in; (void)out_size;
    const float* x  = (const float*)d_in[0];
    const float* Wq = (const float*)d_in[1];
    const float* bq = (const float*)d_in[2];
    const float* Wk = (const float*)d_in[3];
    const float* bk = (const float*)d_in[4];
    const float* Wv = (const float*)d_in[5];
    const float* bv = (const float*)d_in[6];
    const float* Wo = (const float*)d_in[7];
    const float* bo = (const float*)d_in[8];
    float* out = (float*)d_out;

    __half *xh, *wt, *qh, *kh, *vh, *ctxh;
    cudaGetSymbolAddress((void**)&xh,   g_xh);
    cudaGetSymbolAddress((void**)&wt,   g_wt);
    cudaGetSymbolAddress((void**)&qh,   g_qh);
    cudaGetSymbolAddress((void**)&kh,   g_kh);
    cudaGetSymbolAddress((void**)&vh,   g_vh);
    cudaGetSymbolAddress((void**)&ctxh, g_ctxh);
    __half* wqt = wt;
    __half* wkt = wt + (size_t)DD * NHEAD;
    __half* wvt = wt + 2 * (size_t)DD * NHEAD;
    __half* wot = wt + 3 * (size_t)DD * NHEAD;

    cudaFuncSetAttribute(gemm_qkv,
                         cudaFuncAttributeMaxDynamicSharedMemorySize, GSMEM);
    cudaFuncSetAttribute(gemm_f16,
                         cudaFuncAttributeMaxDynamicSharedMemorySize, GSMEM);
    cudaFuncSetAttribute(flash_tc,
                         cudaFuncAttributeMaxDynamicSharedMemorySize, FL_SMEM);

    // Merged prepass: x cvt (8192 blocks) + 4 W transposes (4096 blocks)
    prepass<<<8192 + 4096, 256>>>(x, xh, Wq, Wk, Wv, Wo, wt);

    // Merged QKV projections (128x128 tiles, BK=64); q,k,v fp16 out
    dim3 qkvgrid(NHEAD / GBN, MROWS / GBM, 3);  // (8, 64, 3)
    gemm_qkv<<<qkvgrid, 256, GSMEM>>>(xh, wqt, wkt, wvt, bq, bk, bv,
                                      qh, kh, vh);

    // FP16 flash attention (transpose-free PV via ldmatrix.trans)
    flash_tc<<<dim3(SS / FQ, BB * HH), 256, FL_SMEM>>>(qh, kh, vh, ctxh);

    // Output projection (fp32 out, BK=64)
    dim3 ggrid(NHEAD / GBN, MROWS / GBM);
    gemm_f16<<<ggrid, 256, GSMEM>>>(ctxh, wot, bo, out, 1.0f);
}